// round 15
// baseline (speedup 1.0000x reference)
#include <cuda_runtime.h>
#include <cuda_fp16.h>
#include <cstdint>

// Swin windowed attention: HMMA m16n8k16 (QK fp16-acc, PV fp32-acc),
// E=exp(bias+mask-SHIFT) fp16 in fragment order, fragment-order K/V smem
// (1 LDS.128 each per kk), scalar lsum (no ones-column MMA), 512-thread CTAs.

#define HEADS 8
#define NTOK  256
#define HD    16
#define TPB   512
#define SHIFT 4.0f
#define NWH   512
#define LOG2E 1.44269504f

__device__ float g_B[HEADS * NTOK * NTOK];        // Bh[h][ij] = table[idx,h] - SHIFT
__device__ uint2 g_E2[NWH * 16 * 32 * 32];        // fragment-order exp tiles (67 MB)

#define VSTR 272

static __device__ __forceinline__ void mma_f32(float c[4], const uint32_t a[4], const uint32_t b[2]) {
    asm volatile("mma.sync.aligned.m16n8k16.row.col.f32.f16.f16.f32 "
                 "{%0,%1,%2,%3}, {%4,%5,%6,%7}, {%8,%9}, {%0,%1,%2,%3};"
                 : "+f"(c[0]), "+f"(c[1]), "+f"(c[2]), "+f"(c[3])
                 : "r"(a[0]), "r"(a[1]), "r"(a[2]), "r"(a[3]), "r"(b[0]), "r"(b[1]));
}
static __device__ __forceinline__ void mma_f16(uint32_t c[2], const uint32_t a[4], const uint32_t b[2]) {
    asm volatile("mma.sync.aligned.m16n8k16.row.col.f16.f16.f16.f16 "
                 "{%0,%1}, {%2,%3,%4,%5}, {%6,%7}, {%0,%1};"
                 : "+r"(c[0]), "+r"(c[1])
                 : "r"(a[0]), "r"(a[1]), "r"(a[2]), "r"(a[3]), "r"(b[0]), "r"(b[1]));
}
static __device__ __forceinline__ uint32_t packh2(float x, float y) {
    __half2 h = __floats2half2_rn(x, y);
    return *reinterpret_cast<uint32_t*>(&h);
}

// ---- K1: Bh[h][ij] = table[index[ij]*8 + h] - SHIFT ----
__global__ void gather_bias_kernel(const float* __restrict__ table,
                                   const int* __restrict__ index)
{
    const int ij = blockIdx.x * 256 + threadIdx.x;
    const int idx = index[ij];
    const float4* tr = (const float4*)(table + idx * HEADS);
    float4 t0 = tr[0], t1 = tr[1];
    g_B[0 * 65536 + ij] = t0.x - SHIFT;
    g_B[1 * 65536 + ij] = t0.y - SHIFT;
    g_B[2 * 65536 + ij] = t0.z - SHIFT;
    g_B[3 * 65536 + ij] = t0.w - SHIFT;
    g_B[4 * 65536 + ij] = t1.x - SHIFT;
    g_B[5 * 65536 + ij] = t1.y - SHIFT;
    g_B[6 * 65536 + ij] = t1.z - SHIFT;
    g_B[7 * 65536 + ij] = t1.w - SHIFT;
}

// ---- K2: E2 fragment-order = exp(Bh + mask), via smem transpose ----
__global__ void combine_exp_kernel(const float* __restrict__ mask)
{
    __shared__ __half esm[16][264];
    const int wh = blockIdx.x;
    const int w = wh >> 3, h = wh & 7;
    const int tid = threadIdx.x;
    const float4* bp = (const float4*)(g_B + h * 65536);
    const float4* mp = (const float4*)(mask + (size_t)w * 65536);
    uint2* ep = g_E2 + (size_t)wh * 16384;

    for (int r16 = 0; r16 < 16; r16++) {
        const int base4 = r16 * 1024;
        #pragma unroll
        for (int i = tid; i < 1024; i += 256) {
            const int row = i >> 6;
            const int c4 = (i & 63) * 4;
            float4 bv = bp[base4 + i];
            float4 mv = mp[base4 + i];
            *(uint2*)&esm[row][c4] = make_uint2(
                packh2(__expf(bv.x + mv.x), __expf(bv.y + mv.y)),
                packh2(__expf(bv.z + mv.z), __expf(bv.w + mv.w)));
        }
        __syncthreads();
        #pragma unroll
        for (int i = tid; i < 1024; i += 256) {
            const int nloc = i >> 5;
            const int lane = i & 31;
            const int g = lane >> 2, t4 = lane & 3;
            const int col = nloc * 8 + 2 * t4;
            uint2 o;
            o.x = *(const uint32_t*)&esm[g][col];
            o.y = *(const uint32_t*)&esm[g + 8][col];
            ep[r16 * 1024 + i] = o;
        }
        __syncthreads();
    }
}

__global__ __launch_bounds__(TPB, 2)
void swin_mma_kernel(const float* __restrict__ q, const float* __restrict__ k,
                     const float* __restrict__ v, float* __restrict__ out)
{
    __shared__ __half qh[256 * HD];          // normalized*log2e Q, plain d-order
    __shared__ __half kh[256 * HD];          // normalized K, plain d-order
    __shared__ __half vt[16 * VSTR];         // V^T [dim][key], plain
    __shared__ uint4  kfrag[512];            // [kk][lane] = {nl0.uint2, nl1.uint2}
    __shared__ uint4  vfrag[512];            // [kk][lane] = {nd0.uint2, nd1.uint2}

    const int t   = threadIdx.x;
    const int bid = blockIdx.x;
    const int wh  = bid >> 3;            // 8 images sharing (w,h) adjacent -> E2 L2-resident
    const int img = bid & 7;
    const int w   = wh >> 3, h = wh & 7;
    const int b   = img * 64 + w;
    const int bh  = b * HEADS + h;
    const size_t base = (size_t)bh * NTOK * HD;

    // ---- pass A: stage Q,K normalized (t<256), V^T (t>=256) ----
    if (t < 256) {
        const int r = t;
        {
            const float4* g = (const float4*)(q + base + (size_t)r * HD);
            float4 a0 = g[0], a1 = g[1], a2 = g[2], a3 = g[3];
            float ss = a0.x*a0.x+a0.y*a0.y+a0.z*a0.z+a0.w*a0.w + a1.x*a1.x+a1.y*a1.y+a1.z*a1.z+a1.w*a1.w
                     + a2.x*a2.x+a2.y*a2.y+a2.z*a2.z+a2.w*a2.w + a3.x*a3.x+a3.y*a3.y+a3.z*a3.z+a3.w*a3.w;
            float iv = rsqrtf(fmaxf(ss, 1e-24f)) * LOG2E;
            uint4 u0, u1;
            u0.x = packh2(a0.x*iv, a0.y*iv); u0.y = packh2(a0.z*iv, a0.w*iv);
            u0.z = packh2(a1.x*iv, a1.y*iv); u0.w = packh2(a1.z*iv, a1.w*iv);
            u1.x = packh2(a2.x*iv, a2.y*iv); u1.y = packh2(a2.z*iv, a2.w*iv);
            u1.z = packh2(a3.x*iv, a3.y*iv); u1.w = packh2(a3.z*iv, a3.w*iv);
            uint4* d = (uint4*)(qh + r * HD);
            d[0] = u0; d[1] = u1;
        }
        {
            const float4* g = (const float4*)(k + base + (size_t)r * HD);
            float4 a0 = g[0], a1 = g[1], a2 = g[2], a3 = g[3];
            float ss = a0.x*a0.x+a0.y*a0.y+a0.z*a0.z+a0.w*a0.w + a1.x*a1.x+a1.y*a1.y+a1.z*a1.z+a1.w*a1.w
                     + a2.x*a2.x+a2.y*a2.y+a2.z*a2.z+a2.w*a2.w + a3.x*a3.x+a3.y*a3.y+a3.z*a3.z+a3.w*a3.w;
            float iv = rsqrtf(fmaxf(ss, 1e-24f));
            uint4 u0, u1;
            u0.x = packh2(a0.x*iv, a0.y*iv); u0.y = packh2(a0.z*iv, a0.w*iv);
            u0.z = packh2(a1.x*iv, a1.y*iv); u0.w = packh2(a1.z*iv, a1.w*iv);
            u1.x = packh2(a2.x*iv, a2.y*iv); u1.y = packh2(a2.z*iv, a2.w*iv);
            u1.z = packh2(a3.x*iv, a3.y*iv); u1.w = packh2(a3.z*iv, a3.w*iv);
            uint4* d = (uint4*)(kh + r * HD);
            d[0] = u0; d[1] = u1;
        }
    } else {
        const int r = t - 256;   // key index
        const float4* g = (const float4*)(v + base + (size_t)r * HD);
        float4 a0 = g[0], a1 = g[1], a2 = g[2], a3 = g[3];
        float vd[16] = { a0.x,a0.y,a0.z,a0.w, a1.x,a1.y,a1.z,a1.w,
                         a2.x,a2.y,a2.z,a2.w, a3.x,a3.y,a3.z,a3.w };
        #pragma unroll
        for (int d = 0; d < 16; d++) vt[d * VSTR + r] = __float2half_rn(vd[d]);
    }
    __syncthreads();

    // ---- pass B: repack K and V into per-(kk,lane) MMA fragments ----
    {
        const int kk2  = t >> 5;
        const int lane2 = t & 31;
        const int g2 = lane2 >> 2, t42 = lane2 & 3;
        // K fragment: cols g (nl0: key kk*16+g ; nl1: key kk*16+8+g), k-rows paired by t4
        const int keyA = kk2 * 16 + g2;
        const int keyB = keyA + 8;
        uint4 kf;
        kf.x = *(const uint32_t*)(kh + keyA * HD + 2 * t42);
        kf.y = *(const uint32_t*)(kh + keyA * HD + 2 * t42 + 8);
        kf.z = *(const uint32_t*)(kh + keyB * HD + 2 * t42);
        kf.w = *(const uint32_t*)(kh + keyB * HD + 2 * t42 + 8);
        kfrag[t] = kf;
        // V fragment: k-rows = keys {2t4,2t4+1, 2t4+8,2t4+9} of group kk; cols dims g / g+8
        const int kc = kk2 * 16 + 2 * t42;
        uint4 vf;
        vf.x = *(const uint32_t*)(vt + g2 * VSTR + kc);
        vf.y = *(const uint32_t*)(vt + g2 * VSTR + kc + 8);
        vf.z = *(const uint32_t*)(vt + (g2 + 8) * VSTR + kc);
        vf.w = *(const uint32_t*)(vt + (g2 + 8) * VSTR + kc + 8);
        vfrag[t] = vf;
    }
    __syncthreads();

    // ---- warp-synchronous main loop: 16 warps, one 16-row m-tile each ----
    const int wid  = t >> 5;
    const int lane = t & 31;
    const int g    = lane >> 2;
    const int t4   = lane & 3;
    const int qb   = wid * 16;

    uint32_t qa[4];
    {
        const int row = qb + g;
        qa[0] = *(const uint32_t*)(qh + row * HD + 2 * t4);
        qa[1] = *(const uint32_t*)(qh + (row + 8) * HD + 2 * t4);
        qa[2] = *(const uint32_t*)(qh + row * HD + 2 * t4 + 8);
        qa[3] = *(const uint32_t*)(qh + (row + 8) * HD + 2 * t4 + 8);
    }

    float o[2][4];
    #pragma unroll
    for (int n = 0; n < 2; n++)
        #pragma unroll
        for (int i = 0; i < 4; i++) o[n][i] = 0.f;
    float lsumA = 0.f, lsumB = 0.f;    // rows g, g+8 (this thread's key cols)

    const uint2* Ep = g_E2 + (size_t)wh * 16384 + wid * 1024 + lane;

    #pragma unroll 4
    for (int kk = 0; kk < 16; kk++) {
        uint2 e0 = Ep[(kk * 2 + 0) * 32];
        uint2 e1 = Ep[(kk * 2 + 1) * 32];
        uint4 kb4 = kfrag[kk * 32 + lane];     // LDS.128, conflict-free

        uint32_t sd0[2] = {0u, 0u}, sd1[2] = {0u, 0u};
        {
            uint32_t kb[2] = { kb4.x, kb4.y };
            mma_f16(sd0, qa, kb);
        }
        {
            uint32_t kb[2] = { kb4.z, kb4.w };
            mma_f16(sd1, qa, kb);
        }
        // p = 2^s * E
        __half2 p0 = __hmul2(h2exp2(*(const __half2*)&sd0[0]), *(const __half2*)&e0.x); // row g,   nl0
        __half2 p1 = __hmul2(h2exp2(*(const __half2*)&sd0[1]), *(const __half2*)&e0.y); // row g+8, nl0
        __half2 p2 = __hmul2(h2exp2(*(const __half2*)&sd1[0]), *(const __half2*)&e1.x); // row g,   nl1
        __half2 p3 = __hmul2(h2exp2(*(const __half2*)&sd1[1]), *(const __half2*)&e1.y); // row g+8, nl1
        // scalar lsum (replaces ones-column MMA)
        {
            float2 fA = __half22float2(__hadd2(p0, p2));
            float2 fB = __half22float2(__hadd2(p1, p3));
            lsumA += fA.x + fA.y;
            lsumB += fB.x + fB.y;
        }
        uint32_t pa[4] = { *reinterpret_cast<uint32_t*>(&p0), *reinterpret_cast<uint32_t*>(&p1),
                           *reinterpret_cast<uint32_t*>(&p2), *reinterpret_cast<uint32_t*>(&p3) };

        uint4 vb4 = vfrag[kk * 32 + lane];     // LDS.128, conflict-free
        {
            uint32_t vb[2] = { vb4.x, vb4.y };
            mma_f32(o[0], pa, vb);
        }
        {
            uint32_t vb[2] = { vb4.z, vb4.w };
            mma_f32(o[1], pa, vb);
        }
    }

    // ---- epilogue: quad-reduce lsums, scale, store ----
    lsumA += __shfl_xor_sync(0xFFFFFFFF, lsumA, 1);
    lsumA += __shfl_xor_sync(0xFFFFFFFF, lsumA, 2);
    lsumB += __shfl_xor_sync(0xFFFFFFFF, lsumB, 1);
    lsumB += __shfl_xor_sync(0xFFFFFFFF, lsumB, 2);
    const float inv0 = 1.0f / lsumA;
    const float inv1 = 1.0f / lsumB;
    const int row = qb + g;
    #pragma unroll
    for (int nd = 0; nd < 2; nd++) {
        const int col = h * HD + nd * 8 + 2 * t4;
        float2 v01 = { o[nd][0] * inv0, o[nd][1] * inv0 };
        float2 v23 = { o[nd][2] * inv1, o[nd][3] * inv1 };
        *(float2*)(out + ((size_t)(b * NTOK + row)) * 128 + col)     = v01;
        *(float2*)(out + ((size_t)(b * NTOK + row + 8)) * 128 + col) = v23;
    }
}

extern "C" void kernel_launch(void* const* d_in, const int* in_sizes, int n_in,
                              void* d_out, int out_size)
{
    const float* q     = (const float*)d_in[0];
    const float* k     = (const float*)d_in[1];
    const float* v     = (const float*)d_in[2];
    const float* table = (const float*)d_in[3];
    const int*   index = (const int*)  d_in[4];
    const float* mask  = (const float*)d_in[5];
    float* out = (float*)d_out;

    gather_bias_kernel<<<256, 256>>>(table, index);
    combine_exp_kernel<<<NWH, 256>>>(mask);
    swin_mma_kernel<<<4096, TPB>>>(q, k, v, out);
}